// round 8
// baseline (speedup 1.0000x reference)
#include <cuda_runtime.h>
#include <math.h>

// Problem constants
#define B_ 256
#define N_ 1024
#define H_ 256
#define K_ 5
#define NEG_SLOPE 0.01f
#define FULLMASK 0xffffffffu
#define CHUNKS_PER_B 32          // 32 blocks per batch, 32 nodes each

// Scratch
__device__ float g_key[B_ * N_];
__device__ int   g_done[B_];     // zero-init at load; self-resetting per launch

static __device__ __forceinline__ float neg_inf() {
    return __int_as_float(0xff800000);
}

// ---------------------------------------------------------------------------
// One kernel, 8192 blocks (256 thr). Block = (batch b, chunk c): streams 32
// nodes' maxes into g_key (4 nodes/warp, 8 LDG.128 front-batched). The last
// chunk-block of each batch (threadfence+atomic counter) runs the pool/
// attention epilogue for that batch, overlapped with other batches' streaming.
// ---------------------------------------------------------------------------
__global__ void __launch_bounds__(256)
sortpool_persist_kernel(const float* __restrict__ h,
                        const int* __restrict__ n_nodes,
                        const float* __restrict__ q,
                        const float* __restrict__ W,
                        float* __restrict__ out) {
    __shared__ float s_key[N_];          // 4 KB
    __shared__ float s_sel[K_][H_];      // 5 KB
    __shared__ float s_logit[K_];
    __shared__ float s_cb;
    __shared__ int   s_last;

    const int b     = blockIdx.x >> 5;           // batch
    const int chunk = blockIdx.x & 31;           // 32-node chunk within batch
    const int t     = threadIdx.x;
    const int wid   = t >> 5;
    const int lane  = t & 31;
    const float NI  = neg_inf();
    const int nn    = __ldg(&n_nodes[b]);

    // ============ Phase 1: stream 4 nodes for this warp ============
    {
        const int base = (chunk << 5) + (wid << 2);      // first node of 4
        if (base >= nn) {
            if (lane == 0)
                *reinterpret_cast<float4*>(&g_key[b * N_ + base]) =
                    make_float4(NI, NI, NI, NI);
        } else {
            const float4* p = reinterpret_cast<const float4*>(h) +
                              ((size_t)b * N_ + base) * (H_ / 4);
            float4 va[4], vb[4];
            bool vld[4];
#pragma unroll
            for (int j = 0; j < 4; j++) {
                vld[j] = (base + j) < nn;
                if (vld[j]) {
                    va[j] = p[(j << 6) + lane];
                    vb[j] = p[(j << 6) + lane + 32];
                }
            }
            float m[4];
#pragma unroll
            for (int j = 0; j < 4; j++) {
                m[j] = vld[j]
                     ? fmaxf(fmaxf(fmaxf(va[j].x, va[j].y), fmaxf(va[j].z, va[j].w)),
                             fmaxf(fmaxf(vb[j].x, vb[j].y), fmaxf(vb[j].z, vb[j].w)))
                     : NI;
            }
#pragma unroll
            for (int o = 16; o; o >>= 1) {
#pragma unroll
                for (int j = 0; j < 4; j++)
                    m[j] = fmaxf(m[j], __shfl_xor_sync(FULLMASK, m[j], o));
            }
            if (lane == 0)
                *reinterpret_cast<float4*>(&g_key[b * N_ + base]) =
                    make_float4(m[0], m[1], m[2], m[3]);
        }
    }

    // ============ Handoff: last block of batch b does the pool ============
    __threadfence();                // make this thread's key stores visible
    __syncthreads();                // all warps' stores + fences done
    if (t == 0) {
        int old = atomicAdd(&g_done[b], 1);
        if (old == CHUNKS_PER_B - 1) {
            s_last = 1;
            atomicExch(&g_done[b], 0);   // reset for next graph replay
        } else {
            s_last = 0;
        }
    }
    __syncthreads();
    if (!s_last) return;

    // ============ Phase 2: load keys (L2-coherent) ============
    {
        float4 k4 = __ldcg(reinterpret_cast<const float4*>(g_key + b * N_) + t);
        reinterpret_cast<float4*>(s_key)[t] = k4;
    }
    __syncthreads();   // barrier A

    // ============ Phase 3: top-5 tournament + sort + dots ============
    if (wid < K_) {
        // per-lane top-5 insertion list over 32 strided keys.
        // packed = (ord(float) << 32) | (N-1-i): strict total order ==
        // jax.lax.top_k (value desc, index asc).
        unsigned long long L[K_];
#pragma unroll
        for (int j = 0; j < K_; j++) L[j] = 0ull;
#pragma unroll
        for (int jj = 0; jj < 32; jj++) {
            int i = lane + (jj << 5);                    // conflict-free LDS
            unsigned int bits = __float_as_uint(s_key[i]);
            unsigned int ord  = (bits & 0x80000000u) ? ~bits
                                                     : (bits | 0x80000000u);
            unsigned long long pk =
                ((unsigned long long)ord << 32) | (unsigned int)(N_ - 1 - i);
            if (pk > L[K_ - 1]) {
                L[K_ - 1] = pk;
#pragma unroll
                for (int j2 = K_ - 1; j2 > 0; j2--) {
                    if (L[j2] > L[j2 - 1]) {
                        unsigned long long tmp = L[j2];
                        L[j2] = L[j2 - 1];
                        L[j2 - 1] = tmp;
                    }
                }
            }
        }
        // tournament: warp wid needs rounds 0..wid only
        int p = 0;
        unsigned long long w = 0ull;
        for (int k = 0; k <= wid; k++) {
            w = (p < K_) ? L[p] : 0ull;
#pragma unroll
            for (int o = 16; o; o >>= 1) {
                unsigned long long ow = __shfl_xor_sync(FULLMASK, w, o);
                if (ow > w) w = ow;
            }
            if (p < K_ && L[p] == w) p++;   // unique winner
        }
        const int  node  = (N_ - 1) - (int)(w & 0xffffffffu);
        const bool valid = (unsigned int)(w >> 32) > 0x007fffffu; // > ord(-inf)

        // gather row (L2-hot from phase 1)
        const float* row = h + ((size_t)b * N_ + node) * H_;
        float val[8];
#pragma unroll
        for (int r = 0; r < 8; r++)
            val[r] = valid ? row[(lane << 3) + r] : 0.0f;

        // register bitonic sort, 256 elements, ascending
#pragma unroll
        for (int kk = 2; kk <= 256; kk <<= 1) {
#pragma unroll
            for (int j = kk >> 1; j > 0; j >>= 1) {
                if (j >= 8) {
                    int  ld  = j >> 3;
                    bool asc = (((lane << 3) & kk) == 0);
                    bool low = ((lane & ld) == 0);
#pragma unroll
                    for (int r = 0; r < 8; r++) {
                        float other = __shfl_xor_sync(FULLMASK, val[r], ld);
                        val[r] = (low == asc) ? fminf(val[r], other)
                                              : fmaxf(val[r], other);
                    }
                } else {
#pragma unroll
                    for (int r = 0; r < 8; r++) {
                        if ((r & j) == 0) {
                            int  r2  = r | j;
                            bool asc = ((((lane << 3) | r) & kk) == 0);
                            float a = val[r], c = val[r2];
                            float lo = fminf(a, c), hi = fmaxf(a, c);
                            val[r]  = asc ? lo : hi;
                            val[r2] = asc ? hi : lo;
                        }
                    }
                }
            }
        }

        // store sorted row + raw dot with W[:H]
        float s = 0.0f;
#pragma unroll
        for (int r = 0; r < 8; r++) {
            int i = (lane << 3) + r;
            s_sel[wid][i] = val[r];
            s += val[r] * W[i];
        }
#pragma unroll
        for (int o = 16; o; o >>= 1)
            s += __shfl_xor_sync(FULLMASK, s, o);
        if (lane == 0) s_logit[wid] = s;
    } else if (wid == K_) {
        // cb = dot(q[b,:], W[H:2H])
        float s = 0.0f;
#pragma unroll
        for (int r = 0; r < 8; r++) {
            int i = (lane << 3) + r;
            s += q[b * H_ + i] * W[H_ + i];
        }
#pragma unroll
        for (int o = 16; o; o >>= 1)
            s += __shfl_xor_sync(FULLMASK, s, o);
        if (lane == 0) s_cb = s;
    }
    __syncthreads();   // barrier B

    // ============ Phase 4: leaky + softmax + weighted sum ============
    const float cb = s_cb;
    float lg[K_];
#pragma unroll
    for (int k = 0; k < K_; k++) {
        float x = s_logit[k] + cb;
        lg[k] = (x >= 0.0f) ? x : NEG_SLOPE * x;
    }
    float lm = lg[0];
#pragma unroll
    for (int k = 1; k < K_; k++) lm = fmaxf(lm, lg[k]);
    float es = 0.0f;
    float e[K_];
#pragma unroll
    for (int k = 0; k < K_; k++) { e[k] = __expf(lg[k] - lm); es += e[k]; }
    float inv = 1.0f / es;
    float acc = 0.0f;
#pragma unroll
    for (int k = 0; k < K_; k++) acc += (e[k] * inv) * s_sel[k][t];

    out[b * H_ + t] = acc;
}

extern "C" void kernel_launch(void* const* d_in, const int* in_sizes, int n_in,
                              void* d_out, int out_size) {
    const float* h  = (const float*)d_in[0];           // [B, N, H]
    const int*   nn = (const int*)d_in[1];             // [B]
    const float* q  = (const float*)d_in[2];           // [B, H]
    const float* W  = (const float*)d_in[3];           // [1, 2H]
    float*       o  = (float*)d_out;                   // [B, H]

    (void)in_sizes; (void)n_in; (void)out_size;

    sortpool_persist_kernel<<<B_ * CHUNKS_PER_B, 256>>>(h, nn, q, W, o);
}

// round 10
// speedup vs baseline: 1.2165x; 1.2165x over previous
#include <cuda_runtime.h>
#include <math.h>

// Problem constants
#define B_ 256
#define N_ 1024
#define H_ 256
#define K_ 5
#define NEG_SLOPE 0.01f
#define FULLMASK 0xffffffffu

// Scratch: per-node sort key (max over channels), -inf for masked nodes.
__device__ float g_key[B_ * N_];

static __device__ __forceinline__ float neg_inf() {
    return __int_as_float(0xff800000);
}

// ---------------------------------------------------------------------------
// Kernel 1: key[b,n] = max_h h[b,n,:]  (or -inf if n >= n_nodes[b])
// One warp per 4 nodes; 8 LDG.128 front-batched (4KB/warp in flight).
// Lane 0 writes the 4 keys as one float4.  (Measured ~6.4 TB/s effective.)
// ---------------------------------------------------------------------------
__global__ void __launch_bounds__(256)
node_max_kernel(const float* __restrict__ h, const int* __restrict__ n_nodes) {
    const int gw   = (blockIdx.x * 256 + threadIdx.x) >> 5;  // warp id
    const int lane = threadIdx.x & 31;
    const int base = gw << 2;                 // first of 4 nodes (same batch)
    const int b    = base >> 10;              // N_ = 1024
    const int n0   = base & (N_ - 1);
    const int nn   = __ldg(&n_nodes[b]);
    const float NI = neg_inf();

    const float4* p = reinterpret_cast<const float4*>(h) + (size_t)base * (H_ / 4);

    float4 va[4], vc[4];
    bool valid[4];
#pragma unroll
    for (int j = 0; j < 4; j++) {
        valid[j] = (n0 + j) < nn;
        if (valid[j]) {
            va[j] = p[(j << 6) + lane];
            vc[j] = p[(j << 6) + lane + 32];
        }
    }

    float m[4];
#pragma unroll
    for (int j = 0; j < 4; j++) {
        if (valid[j]) {
            m[j] = fmaxf(fmaxf(fmaxf(va[j].x, va[j].y), fmaxf(va[j].z, va[j].w)),
                         fmaxf(fmaxf(vc[j].x, vc[j].y), fmaxf(vc[j].z, vc[j].w)));
        } else {
            m[j] = NI;
        }
    }

#pragma unroll
    for (int o = 16; o; o >>= 1) {
#pragma unroll
        for (int j = 0; j < 4; j++)
            m[j] = fmaxf(m[j], __shfl_xor_sync(FULLMASK, m[j], o));
    }

    if (lane == 0) {
        *reinterpret_cast<float4*>(&g_key[base]) =
            make_float4(m[0], m[1], m[2], m[3]);
    }
}

// ---------------------------------------------------------------------------
// Kernel 2 (2 block barriers):
//  - all warps load the 1024 keys into shared (one float4/thread)
//  - warps 0..4 IN PARALLEL: per-lane u64-packed top-5 insertion lists +
//    shuffle tournament with strict total order == jax.lax.top_k semantics
//    (value desc, index asc); warp wid exits at round wid, gathers its row,
//    register-bitonic sorts it, dots with W[:H]. Warp 5: cb = dot(q,W[H:2H]).
//  - all threads: leaky + softmax over K + weighted sum.
// ---------------------------------------------------------------------------
__global__ void __launch_bounds__(256)
pool_attn_kernel(const float* __restrict__ h,
                 const float* __restrict__ q,
                 const float* __restrict__ W,
                 float* __restrict__ out) {
    __shared__ float s_key[N_];          // 4 KB
    __shared__ float s_sel[K_][H_];      // 5 KB: sorted selected rows
    __shared__ float s_logit[K_];        // raw dot (pre-cb, pre-leaky)
    __shared__ float s_cb;

    const int b    = blockIdx.x;
    const int t    = threadIdx.x;
    const int wid  = t >> 5;
    const int lane = t & 31;

    // ---- load keys (one float4 per thread, coalesced) ----
    reinterpret_cast<float4*>(s_key)[t] =
        reinterpret_cast<const float4*>(g_key + b * N_)[t];
    __syncthreads();   // barrier A

    if (wid < K_) {
        // ---- per-lane top-5 insertion list over 32 strided keys ----
        // packed = (ord(float) << 32) | (N-1-i): strict total order,
        // value desc then index asc — identical to jax.lax.top_k.
        unsigned long long L[K_];
#pragma unroll
        for (int j = 0; j < K_; j++) L[j] = 0ull;
#pragma unroll
        for (int jj = 0; jj < 32; jj++) {
            int i = lane + (jj << 5);                    // conflict-free LDS
            unsigned int bits = __float_as_uint(s_key[i]);
            unsigned int ord  = (bits & 0x80000000u) ? ~bits
                                                     : (bits | 0x80000000u);
            unsigned long long pk =
                ((unsigned long long)ord << 32) | (unsigned int)(N_ - 1 - i);
            if (pk > L[K_ - 1]) {
                L[K_ - 1] = pk;
#pragma unroll
                for (int j2 = K_ - 1; j2 > 0; j2--) {
                    if (L[j2] > L[j2 - 1]) {
                        unsigned long long tmp = L[j2];
                        L[j2] = L[j2 - 1];
                        L[j2 - 1] = tmp;
                    }
                }
            }
        }
        // ---- tournament: warp wid needs rounds 0..wid only ----
        int p = 0;
        unsigned long long w = 0ull;
        for (int k = 0; k <= wid; k++) {
            w = (p < K_) ? L[p] : 0ull;
#pragma unroll
            for (int o = 16; o; o >>= 1) {
                unsigned long long ow = __shfl_xor_sync(FULLMASK, w, o);
                if (ow > w) w = ow;
            }
            if (p < K_ && L[p] == w) p++;   // unique winner (indices distinct)
        }
        const int  node  = (N_ - 1) - (int)(w & 0xffffffffu);
        const bool valid = (unsigned int)(w >> 32) > 0x007fffffu; // > ord(-inf)

        // ---- gather row (L2-hot from kernel 1) ----
        const float* row = h + ((size_t)b * N_ + node) * H_;
        float val[8];
#pragma unroll
        for (int r = 0; r < 8; r++)
            val[r] = valid ? row[(lane << 3) + r] : 0.0f;

        // ---- register bitonic sort, 256 elements, ascending ----
#pragma unroll
        for (int kk = 2; kk <= 256; kk <<= 1) {
#pragma unroll
            for (int j = kk >> 1; j > 0; j >>= 1) {
                if (j >= 8) {
                    int  ld  = j >> 3;
                    bool asc = (((lane << 3) & kk) == 0);
                    bool low = ((lane & ld) == 0);
#pragma unroll
                    for (int r = 0; r < 8; r++) {
                        float other = __shfl_xor_sync(FULLMASK, val[r], ld);
                        val[r] = (low == asc) ? fminf(val[r], other)
                                              : fmaxf(val[r], other);
                    }
                } else {
#pragma unroll
                    for (int r = 0; r < 8; r++) {
                        if ((r & j) == 0) {
                            int  r2  = r | j;
                            bool asc = ((((lane << 3) | r) & kk) == 0);
                            float a = val[r], c = val[r2];
                            float lo = fminf(a, c), hi = fmaxf(a, c);
                            val[r]  = asc ? lo : hi;
                            val[r2] = asc ? hi : lo;
                        }
                    }
                }
            }
        }

        // ---- store sorted row + raw dot with W[:H] ----
        float s = 0.0f;
#pragma unroll
        for (int r = 0; r < 8; r++) {
            int i = (lane << 3) + r;
            s_sel[wid][i] = val[r];
            s += val[r] * W[i];
        }
#pragma unroll
        for (int o = 16; o; o >>= 1)
            s += __shfl_xor_sync(FULLMASK, s, o);
        if (lane == 0) s_logit[wid] = s;
    } else if (wid == K_) {
        // ---- cb = dot(q[b,:], W[H:2H]) ----
        float s = 0.0f;
#pragma unroll
        for (int r = 0; r < 8; r++) {
            int i = (lane << 3) + r;
            s += q[b * H_ + i] * W[H_ + i];
        }
#pragma unroll
        for (int o = 16; o; o >>= 1)
            s += __shfl_xor_sync(FULLMASK, s, o);
        if (lane == 0) s_cb = s;
    }
    __syncthreads();   // barrier B

    // ---- leaky + softmax over K + weighted sum (thread t owns channel t) ----
    const float cb = s_cb;
    float lg[K_];
#pragma unroll
    for (int k = 0; k < K_; k++) {
        float x = s_logit[k] + cb;
        lg[k] = (x >= 0.0f) ? x : NEG_SLOPE * x;
    }
    float lm = lg[0];
#pragma unroll
    for (int k = 1; k < K_; k++) lm = fmaxf(lm, lg[k]);
    float es = 0.0f;
    float e[K_];
#pragma unroll
    for (int k = 0; k < K_; k++) { e[k] = __expf(lg[k] - lm); es += e[k]; }
    float inv = 1.0f / es;
    float acc = 0.0f;
#pragma unroll
    for (int k = 0; k < K_; k++) acc += (e[k] * inv) * s_sel[k][t];

    out[b * H_ + t] = acc;
}

extern "C" void kernel_launch(void* const* d_in, const int* in_sizes, int n_in,
                              void* d_out, int out_size) {
    const float* h  = (const float*)d_in[0];           // [B, N, H]
    const int*   nn = (const int*)d_in[1];             // [B]
    const float* q  = (const float*)d_in[2];           // [B, H]
    const float* W  = (const float*)d_in[3];           // [1, 2H]
    float*       o  = (float*)d_out;                   // [B, H]

    (void)in_sizes; (void)n_in; (void)out_size;

    // Kernel 1: 4 nodes per warp, 8 warps/block -> 32 nodes/block
    node_max_kernel<<<(B_ * N_) / 32, 256>>>(h, nn);
    // Kernel 2: one block per batch
    pool_attn_kernel<<<B_, 256>>>(h, q, W, o);
}

// round 11
// speedup vs baseline: 1.4726x; 1.2105x over previous
#include <cuda_runtime.h>
#include <math.h>

// Problem constants
#define B_ 256
#define N_ 1024
#define H_ 256
#define K_ 5
#define NEG_SLOPE 0.01f
#define FULLMASK 0xffffffffu

// Scratch: per-node sort key (max over channels), -inf for masked nodes.
__device__ float g_key[B_ * N_];

static __device__ __forceinline__ float neg_inf() {
    return __int_as_float(0xff800000);
}

// u64 butterfly max over the warp (5 rounds)
static __device__ __forceinline__ unsigned long long
warp_max_u64(unsigned long long w) {
#pragma unroll
    for (int o = 16; o; o >>= 1) {
        unsigned long long ow = __shfl_xor_sync(FULLMASK, w, o);
        if (ow > w) w = ow;
    }
    return w;
}

// ---------------------------------------------------------------------------
// Kernel 1: key[b,n] = max_h h[b,n,:]  (or -inf if n >= n_nodes[b])
// One warp per 4 nodes; 8 LDG.128 front-batched (4KB/warp in flight).
// ---------------------------------------------------------------------------
__global__ void __launch_bounds__(256)
node_max_kernel(const float* __restrict__ h, const int* __restrict__ n_nodes) {
    const int gw   = (blockIdx.x * 256 + threadIdx.x) >> 5;  // warp id
    const int lane = threadIdx.x & 31;
    const int base = gw << 2;                 // first of 4 nodes (same batch)
    const int b    = base >> 10;              // N_ = 1024
    const int n0   = base & (N_ - 1);
    const int nn   = __ldg(&n_nodes[b]);
    const float NI = neg_inf();

    const float4* p = reinterpret_cast<const float4*>(h) + (size_t)base * (H_ / 4);

    float4 va[4], vc[4];
    bool valid[4];
#pragma unroll
    for (int j = 0; j < 4; j++) {
        valid[j] = (n0 + j) < nn;
        if (valid[j]) {
            va[j] = p[(j << 6) + lane];
            vc[j] = p[(j << 6) + lane + 32];
        }
    }

    float m[4];
#pragma unroll
    for (int j = 0; j < 4; j++) {
        if (valid[j]) {
            m[j] = fmaxf(fmaxf(fmaxf(va[j].x, va[j].y), fmaxf(va[j].z, va[j].w)),
                         fmaxf(fmaxf(vc[j].x, vc[j].y), fmaxf(vc[j].z, vc[j].w)));
        } else {
            m[j] = NI;
        }
    }

#pragma unroll
    for (int o = 16; o; o >>= 1) {
#pragma unroll
        for (int j = 0; j < 4; j++)
            m[j] = fmaxf(m[j], __shfl_xor_sync(FULLMASK, m[j], o));
    }

    if (lane == 0) {
        *reinterpret_cast<float4*>(&g_key[base]) =
            make_float4(m[0], m[1], m[2], m[3]);
    }
}

// ---------------------------------------------------------------------------
// Kernel 2 (2 block barriers, short critical path):
//  Stage 1 (all 8 warps in parallel): warp w loads its 128 contiguous keys
//    (one float4/lane, coalesced), packs u64 (ord<<32 | N-1-i) == top_k's
//    (value desc, index asc) total order, runs 5 branchless max-with-consume
//    passes over 4 register values/lane; lane 0 stores the warp's 5 winners.
//  Stage 2 (warps 0..4): merge the 40 candidates (2/lane in registers) with
//    wid+1 max-with-consume rounds; warp wid exits at its round and gathers
//    its row. Warp 5: cb = dot(q, W[H:2H]).
//  Stage 3: register bitonic sort (8/lane), dot with W[:H] -> s_logit.
//  Stage 4: per-thread leaky + softmax over K + weighted sum.
// ---------------------------------------------------------------------------
__global__ void __launch_bounds__(256)
pool_attn_kernel(const float* __restrict__ h,
                 const float* __restrict__ q,
                 const float* __restrict__ W,
                 float* __restrict__ out) {
    __shared__ unsigned long long s_cand[8 * K_];   // 40 candidates
    __shared__ float s_sel[K_][H_];                 // sorted selected rows
    __shared__ float s_logit[K_];                   // raw dot (pre-cb)
    __shared__ float s_cb;

    const int b    = blockIdx.x;
    const int t    = threadIdx.x;
    const int wid  = t >> 5;
    const int lane = t & 31;

    // ===== Stage 1: per-warp top-5 of its 128-key slice =====
    {
        // keys for indices i0..i0+3, contiguous float4 per lane (coalesced)
        const int i0 = (wid << 7) + (lane << 2);
        float4 kv = *reinterpret_cast<const float4*>(&g_key[b * N_ + i0]);

        unsigned long long pk[4];
        float kf[4] = {kv.x, kv.y, kv.z, kv.w};
#pragma unroll
        for (int r = 0; r < 4; r++) {
            unsigned int bits = __float_as_uint(kf[r]);
            unsigned int ord  = (bits & 0x80000000u) ? ~bits
                                                     : (bits | 0x80000000u);
            pk[r] = ((unsigned long long)ord << 32) |
                    (unsigned int)(N_ - 1 - (i0 + r));
        }

#pragma unroll
        for (int k = 0; k < K_; k++) {
            unsigned long long m = pk[0];
            if (pk[1] > m) m = pk[1];
            if (pk[2] > m) m = pk[2];
            if (pk[3] > m) m = pk[3];
            unsigned long long w = warp_max_u64(m);
            if (lane == 0) s_cand[wid * K_ + k] = w;
            // consume winner (unique: index bits distinct)
#pragma unroll
            for (int r = 0; r < 4; r++)
                if (pk[r] == w) pk[r] = 0ull;
        }
    }
    __syncthreads();   // barrier A

    // ===== Stage 2 + 3 =====
    if (wid < K_) {
        // 40 candidates: lane holds c0 = cand[lane], c1 = cand[32+lane] (lane<8)
        unsigned long long c0 = s_cand[lane];
        unsigned long long c1 = (lane < 8) ? s_cand[32 + lane] : 0ull;

        unsigned long long w = 0ull;
        for (int k = 0; k <= wid; k++) {
            unsigned long long m = (c0 > c1) ? c0 : c1;
            w = warp_max_u64(m);
            if (c0 == w) c0 = 0ull;
            else if (c1 == w) c1 = 0ull;
        }
        const int  node  = (N_ - 1) - (int)(w & 0xffffffffu);
        const bool valid = (unsigned int)(w >> 32) > 0x007fffffu; // > ord(-inf)

        // ---- gather row ----
        const float* row = h + ((size_t)b * N_ + node) * H_;
        float val[8];
#pragma unroll
        for (int r = 0; r < 8; r++)
            val[r] = valid ? row[(lane << 3) + r] : 0.0f;

        // ---- register bitonic sort, 256 elements, ascending ----
#pragma unroll
        for (int kk = 2; kk <= 256; kk <<= 1) {
#pragma unroll
            for (int j = kk >> 1; j > 0; j >>= 1) {
                if (j >= 8) {
                    int  ld  = j >> 3;
                    bool asc = (((lane << 3) & kk) == 0);
                    bool low = ((lane & ld) == 0);
#pragma unroll
                    for (int r = 0; r < 8; r++) {
                        float other = __shfl_xor_sync(FULLMASK, val[r], ld);
                        val[r] = (low == asc) ? fminf(val[r], other)
                                              : fmaxf(val[r], other);
                    }
                } else {
#pragma unroll
                    for (int r = 0; r < 8; r++) {
                        if ((r & j) == 0) {
                            int  r2  = r | j;
                            bool asc = ((((lane << 3) | r) & kk) == 0);
                            float a = val[r], c = val[r2];
                            float lo = fminf(a, c), hi = fmaxf(a, c);
                            val[r]  = asc ? lo : hi;
                            val[r2] = asc ? hi : lo;
                        }
                    }
                }
            }
        }

        // ---- store sorted row + raw dot with W[:H] ----
        float s = 0.0f;
#pragma unroll
        for (int r = 0; r < 8; r++) {
            int i = (lane << 3) + r;
            s_sel[wid][i] = val[r];
            s += val[r] * W[i];
        }
#pragma unroll
        for (int o = 16; o; o >>= 1)
            s += __shfl_xor_sync(FULLMASK, s, o);
        if (lane == 0) s_logit[wid] = s;
    } else if (wid == K_) {
        // ---- cb = dot(q[b,:], W[H:2H]) ----
        float s = 0.0f;
#pragma unroll
        for (int r = 0; r < 8; r++) {
            int i = (lane << 3) + r;
            s += q[b * H_ + i] * W[H_ + i];
        }
#pragma unroll
        for (int o = 16; o; o >>= 1)
            s += __shfl_xor_sync(FULLMASK, s, o);
        if (lane == 0) s_cb = s;
    }
    __syncthreads();   // barrier B

    // ===== Stage 4: leaky + softmax over K + weighted sum =====
    const float cb = s_cb;
    float lg[K_];
#pragma unroll
    for (int k = 0; k < K_; k++) {
        float x = s_logit[k] + cb;
        lg[k] = (x >= 0.0f) ? x : NEG_SLOPE * x;
    }
    float lm = lg[0];
#pragma unroll
    for (int k = 1; k < K_; k++) lm = fmaxf(lm, lg[k]);
    float es = 0.0f;
    float e[K_];
#pragma unroll
    for (int k = 0; k < K_; k++) { e[k] = __expf(lg[k] - lm); es += e[k]; }
    float inv = 1.0f / es;
    float acc = 0.0f;
#pragma unroll
    for (int k = 0; k < K_; k++) acc += (e[k] * inv) * s_sel[k][t];

    out[b * H_ + t] = acc;
}

extern "C" void kernel_launch(void* const* d_in, const int* in_sizes, int n_in,
                              void* d_out, int out_size) {
    const float* h  = (const float*)d_in[0];           // [B, N, H]
    const int*   nn = (const int*)d_in[1];             // [B]
    const float* q  = (const float*)d_in[2];           // [B, H]
    const float* W  = (const float*)d_in[3];           // [1, 2H]
    float*       o  = (float*)d_out;                   // [B, H]

    (void)in_sizes; (void)n_in; (void)out_size;

    // Kernel 1: 4 nodes per warp, 8 warps/block -> 32 nodes/block
    node_max_kernel<<<(B_ * N_) / 32, 256>>>(h, nn);
    // Kernel 2: one block per batch
    pool_attn_kernel<<<B_, 256>>>(h, q, W, o);
}